// round 1
// baseline (speedup 1.0000x reference)
#include <cuda_runtime.h>
#include <math.h>

#define S_LEN 2048
#define DDIM  128
#define BM    64
#define BN    64
#define NTHREADS 256

// smem layout (floats):
//  Qt: [128][64]  k-major, XOR-quad swizzled
//  Kt: [128][64]  k-major, XOR-quad swizzled
//  Pt: [64][64]   j-major, XOR-quad swizzled
//  Vs: [64][128]  row-major
#define QT_OFF 0
#define KT_OFF (128*64)
#define PT_OFF (KT_OFF + 128*64)
#define VS_OFF (PT_OFF + 64*64)
#define SMEM_FLOATS (VS_OFF + 64*128)
#define SMEM_BYTES  (SMEM_FLOATS * 4)

__global__ __launch_bounds__(NTHREADS, 1)
void attn_kernel(const float* __restrict__ Q, const float* __restrict__ K,
                 const float* __restrict__ V, float* __restrict__ O) {
    extern __shared__ float smem[];
    float* Qt = smem + QT_OFF;
    float* Kt = smem + KT_OFF;
    float* Pt = smem + PT_OFF;
    float* Vs = smem + VS_OFF;

    const int qt    = blockIdx.x;
    const int b     = blockIdx.y;
    const int qbase = qt * BM;
    const int tid   = threadIdx.x;
    const int tx    = tid & 15;   // 0..15
    const int ty    = tid >> 4;   // 0..15

    const float* Qg = Q + (size_t)b * S_LEN * DDIM;
    const float* Kg = K + (size_t)b * S_LEN * DDIM;
    const float* Vg = V + (size_t)b * S_LEN * DDIM;
    float*       Og = O + (size_t)b * S_LEN * DDIM;

    // ---- load Q tile, transposed k-major with XOR-quad swizzle ----
    for (int i = tid; i < BM * DDIM; i += NTHREADS) {
        int m = i >> 7;         // tile row
        int k = i & 127;        // dim
        float v = Qg[(qbase + m) * DDIM + k];
        Qt[k * 64 + ((((m >> 2) ^ (k & 15)) << 2) | (m & 3))] = v;
    }

    float o[32];
    #pragma unroll
    for (int i = 0; i < 32; i++) o[i] = 0.f;
    float mrow[4], lrow[4];
    #pragma unroll
    for (int r = 0; r < 4; r++) { mrow[r] = -INFINITY; lrow[r] = 0.f; }

    const float qk_scale = 0.0883883476483184405f;   // 1/sqrt(128)

    const int ntiles = qt + 1;                       // causal: only tiles with valid keys
    for (int t = 0; t < ntiles; t++) {
        const int kb = t * BN;
        __syncthreads();   // previous iteration done with Kt/Vs/Pt

        // ---- load K tile (transposed+swizzled) and V tile (row-major) ----
        for (int i = tid; i < BN * DDIM; i += NTHREADS) {
            int n = i >> 7;
            int k = i & 127;
            Kt[k * 64 + ((((n >> 2) ^ (k & 15)) << 2) | (n & 3))] = Kg[(kb + n) * DDIM + k];
        }
        for (int i = tid * 4; i < BN * DDIM; i += NTHREADS * 4) {
            *(float4*)&Vs[i] = *(const float4*)&Vg[kb * DDIM + i];
        }
        __syncthreads();

        // ---- S = Q K^T  (64x64x128, 4x4 micro-tile) ----
        float s[4][4];
        #pragma unroll
        for (int r = 0; r < 4; r++)
            #pragma unroll
            for (int c = 0; c < 4; c++) s[r][c] = 0.f;

        #pragma unroll 4
        for (int k = 0; k < DDIM; k++) {
            float4 af = *(float4*)&Qt[k * 64 + ((ty ^ (k & 15)) << 2)];
            float4 bf = *(float4*)&Kt[k * 64 + ((tx ^ (k & 15)) << 2)];
            float av[4] = {af.x, af.y, af.z, af.w};
            float bv[4] = {bf.x, bf.y, bf.z, bf.w};
            #pragma unroll
            for (int r = 0; r < 4; r++)
                #pragma unroll
                for (int c = 0; c < 4; c++)
                    s[r][c] += av[r] * bv[c];
        }

        // ---- scale + causal mask (only diagonal tile needs it) ----
        const bool diag = (kb + BN > qbase);
        #pragma unroll
        for (int r = 0; r < 4; r++) {
            int grow = qbase + ty * 4 + r;
            #pragma unroll
            for (int c = 0; c < 4; c++) {
                int gcol = kb + tx * 4 + c;
                float v = s[r][c] * qk_scale;
                if (diag && gcol > grow) v = -1e9f;   // matches reference MASK_FILL
                s[r][c] = v;
            }
        }

        // ---- online softmax (row reductions over the 16 tx-threads = half warp) ----
        float alpha[4];
        #pragma unroll
        for (int r = 0; r < 4; r++) {
            float mx = fmaxf(fmaxf(s[r][0], s[r][1]), fmaxf(s[r][2], s[r][3]));
            #pragma unroll
            for (int off = 8; off >= 1; off >>= 1)
                mx = fmaxf(mx, __shfl_xor_sync(0xffffffffu, mx, off, 16));
            float mnew = fmaxf(mrow[r], mx);
            alpha[r] = __expf(mrow[r] - mnew);        // first tile: exp(-inf)=0
            mrow[r] = mnew;
            float sum = 0.f;
            #pragma unroll
            for (int c = 0; c < 4; c++) {
                float p = __expf(s[r][c] - mnew);     // masked: exp(~-1e9)=0 exactly
                s[r][c] = p;
                sum += p;
            }
            #pragma unroll
            for (int off = 8; off >= 1; off >>= 1)
                sum += __shfl_xor_sync(0xffffffffu, sum, off, 16);
            lrow[r] = lrow[r] * alpha[r] + sum;
        }

        // ---- rescale running O ----
        #pragma unroll
        for (int r = 0; r < 4; r++)
            #pragma unroll
            for (int c = 0; c < 8; c++)
                o[r * 8 + c] *= alpha[r];

        // ---- store P transposed+swizzled ----
        #pragma unroll
        for (int c = 0; c < 4; c++) {
            int j = tx * 4 + c;
            #pragma unroll
            for (int r = 0; r < 4; r++)
                Pt[j * 64 + (((ty ^ (j & 15)) << 2) | r)] = s[r][c];
        }
        __syncthreads();

        // ---- O += P V  (64x128x64, 4x8 micro-tile; cols split into two halves) ----
        #pragma unroll 2
        for (int j = 0; j < BN; j++) {
            float4 af = *(float4*)&Pt[j * 64 + ((ty ^ (j & 15)) << 2)];
            float4 b0 = *(float4*)&Vs[j * DDIM + tx * 4];
            float4 b1 = *(float4*)&Vs[j * DDIM + 64 + tx * 4];
            float av[4] = {af.x, af.y, af.z, af.w};
            float bv[8] = {b0.x, b0.y, b0.z, b0.w, b1.x, b1.y, b1.z, b1.w};
            #pragma unroll
            for (int r = 0; r < 4; r++)
                #pragma unroll
                for (int c = 0; c < 8; c++)
                    o[r * 8 + c] += av[r] * bv[c];
        }
    }

    // ---- epilogue: normalize and store ----
    #pragma unroll
    for (int r = 0; r < 4; r++) {
        float inv = 1.f / lrow[r];
        int grow = qbase + ty * 4 + r;
        float4 v0 = make_float4(o[r*8+0]*inv, o[r*8+1]*inv, o[r*8+2]*inv, o[r*8+3]*inv);
        float4 v1 = make_float4(o[r*8+4]*inv, o[r*8+5]*inv, o[r*8+6]*inv, o[r*8+7]*inv);
        *(float4*)&Og[grow * DDIM + tx * 4]      = v0;
        *(float4*)&Og[grow * DDIM + 64 + tx * 4] = v1;
    }
}

extern "C" void kernel_launch(void* const* d_in, const int* in_sizes, int n_in,
                              void* d_out, int out_size) {
    const float* Q = (const float*)d_in[0];
    const float* K = (const float*)d_in[1];
    const float* V = (const float*)d_in[2];
    float*       O = (float*)d_out;

    int B = in_sizes[0] / (S_LEN * DDIM);

    cudaFuncSetAttribute(attn_kernel, cudaFuncAttributeMaxDynamicSharedMemorySize, SMEM_BYTES);

    dim3 grid(S_LEN / BM, B);
    attn_kernel<<<grid, NTHREADS, SMEM_BYTES>>>(Q, K, V, O);
}